// round 7
// baseline (speedup 1.0000x reference)
#include <cuda_runtime.h>
#include <cstdint>

namespace {

constexpr int NTH  = 256;
constexpr int NCTA = 2048;   // each CTA handles 2 data blocks
constexpr int ROWS = 1024;

typedef unsigned long long u64;

// packed f32x2 helpers (sm_103a; PTX-only, ptxas never auto-fuses)
__device__ __forceinline__ u64 pk2(float lo, float hi) {
    u64 d; asm("mov.b64 %0, {%1, %2};" : "=l"(d) : "f"(lo), "f"(hi)); return d;
}
__device__ __forceinline__ void upk2(float& lo, float& hi, u64 p) {
    asm("mov.b64 {%0, %1}, %2;" : "=f"(lo), "=f"(hi) : "l"(p));
}
__device__ __forceinline__ u64 fma2(u64 a, u64 b, u64 c) {
    u64 d; asm("fma.rn.f32x2 %0, %1, %2, %3;" : "=l"(d) : "l"(a), "l"(b), "l"(c)); return d;
}
__device__ __forceinline__ u64 add2(u64 a, u64 b) {
    u64 d; asm("add.rn.f32x2 %0, %1, %2;" : "=l"(d) : "l"(a), "l"(b)); return d;
}
__device__ __forceinline__ float cnrm(const float4 c) {
    return fmaf(c.w, c.w, fmaf(c.z, c.z, fmaf(c.y, c.y, c.x * c.x)));
}

__global__ __launch_bounds__(NTH, 5)
void viterbi_kernel(const float* __restrict__ array,
                    const float* __restrict__ codebook,
                    float* __restrict__ out,
                    int out_size)
{
    __shared__ float alphaA[2][1024];
    __shared__ float alphaB[2][1024];
    __shared__ ulonglong2 xsdA[64][2];      // -2*x, components duplicated as pairs
    __shared__ ulonglong2 xsdB[64][2];
    __shared__ unsigned char bp[64][NTH];   // jA in bits[1:0], jB in bits[3:2]
    __shared__ int   pathA[64], pathB[64];
    __shared__ float redvA[8], redvB[8];
    __shared__ int   rediA[8], rediB[8];

    const int k  = threadIdx.x;             // state group: owns states 4k..4k+3
    const int bA = 2 * blockIdx.x;
    const int bB = bA + 1;
    const int brA = bA >> 6, bcA = bA & 63;
    const int brB = bB >> 6, bcB = bB & 63;

    // ---- load both blocks' elements, pre-scaled by -2, duplicated pairs ----
    {
        int r = k >> 4, cc = k & 15;
        float vA = -2.0f * array[(brA * 16 + r) * ROWS + (bcA * 16 + cc)];
        float vB = -2.0f * array[(brB * 16 + r) * ROWS + (bcB * 16 + cc)];
        reinterpret_cast<u64*>(&xsdA[k >> 2][0])[k & 3] = pk2(vA, vA);
        reinterpret_cast<u64*>(&xsdB[k >> 2][0])[k & 3] = pk2(vB, vB);
    }

    // ---- codebook rows 4k..4k+3 -> (even,odd) packed pairs (shared by both chains) ----
    const float4* cb4 = reinterpret_cast<const float4*>(codebook);
    float4 o0 = __ldg(cb4 + 4 * k + 0);
    float4 o1 = __ldg(cb4 + 4 * k + 1);
    float4 o2 = __ldg(cb4 + 4 * k + 2);
    float4 o3 = __ldg(cb4 + 4 * k + 3);
    u64 cx01 = pk2(o0.x, o1.x), cy01 = pk2(o0.y, o1.y), cz01 = pk2(o0.z, o1.z), cw01 = pk2(o0.w, o1.w);
    u64 cx23 = pk2(o2.x, o3.x), cy23 = pk2(o2.y, o3.y), cz23 = pk2(o2.z, o3.z), cw23 = pk2(o2.w, o3.w);
    u64 cn01 = pk2(cnrm(o0), cnrm(o1));
    u64 cn23 = pk2(cnrm(o2), cnrm(o3));

    __syncthreads();

    // ---- alpha_0 = cost(x0) for both blocks ----
    u64 vA01, vA23, vB01, vB23;
    {
        ulonglong2 xa0 = xsdA[0][0], xa1 = xsdA[0][1];
        ulonglong2 xb0 = xsdB[0][0], xb1 = xsdB[0][1];
        vA01 = fma2(cw01, xa1.y, fma2(cz01, xa1.x, fma2(cy01, xa0.y, fma2(cx01, xa0.x, cn01))));
        vA23 = fma2(cw23, xa1.y, fma2(cz23, xa1.x, fma2(cy23, xa0.y, fma2(cx23, xa0.x, cn23))));
        vB01 = fma2(cw01, xb1.y, fma2(cz01, xb1.x, fma2(cy01, xb0.y, fma2(cx01, xb0.x, cn01))));
        vB23 = fma2(cw23, xb1.y, fma2(cz23, xb1.x, fma2(cy23, xb0.y, fma2(cx23, xb0.x, cn23))));
        *reinterpret_cast<ulonglong2*>(&alphaA[0][4 * k]) = make_ulonglong2(vA01, vA23);
        *reinterpret_cast<ulonglong2*>(&alphaB[0][4 * k]) = make_ulonglong2(vB01, vB23);
    }
    __syncthreads();

    // ---- forward recursion: 63 steps, two independent packed chains ----
#pragma unroll 2
    for (int t = 1; t < 64; ++t) {
        const float* apA = alphaA[(t + 1) & 1];
        const float* apB = alphaB[(t + 1) & 1];
        float aA0 = apA[k], aA1 = apA[k + 256], aA2 = apA[k + 512], aA3 = apA[k + 768];
        float aB0 = apB[k], aB1 = apB[k + 256], aB2 = apB[k + 512], aB3 = apB[k + 768];

        float mA = aA0; int jA = 0;          // strict < -> first-occurrence argmin
        if (aA1 < mA) { mA = aA1; jA = 1; }
        if (aA2 < mA) { mA = aA2; jA = 2; }
        if (aA3 < mA) { mA = aA3; jA = 3; }
        float mB = aB0; int jB = 0;
        if (aB1 < mB) { mB = aB1; jB = 1; }
        if (aB2 < mB) { mB = aB2; jB = 2; }
        if (aB3 < mB) { mB = aB3; jB = 3; }
        bp[t][k] = (unsigned char)(jA | (jB << 2));

        ulonglong2 xa0 = xsdA[t][0], xa1 = xsdA[t][1];
        ulonglong2 xb0 = xsdB[t][0], xb1 = xsdB[t][1];
        u64 mmA = pk2(mA, mA);
        u64 mmB = pk2(mB, mB);
        u64 cA01 = fma2(cw01, xa1.y, fma2(cz01, xa1.x, fma2(cy01, xa0.y, fma2(cx01, xa0.x, cn01))));
        u64 cA23 = fma2(cw23, xa1.y, fma2(cz23, xa1.x, fma2(cy23, xa0.y, fma2(cx23, xa0.x, cn23))));
        u64 cB01 = fma2(cw01, xb1.y, fma2(cz01, xb1.x, fma2(cy01, xb0.y, fma2(cx01, xb0.x, cn01))));
        u64 cB23 = fma2(cw23, xb1.y, fma2(cz23, xb1.x, fma2(cy23, xb0.y, fma2(cx23, xb0.x, cn23))));
        vA01 = add2(mmA, cA01);
        vA23 = add2(mmA, cA23);
        vB01 = add2(mmB, cB01);
        vB23 = add2(mmB, cB23);
        *reinterpret_cast<ulonglong2*>(&alphaA[t & 1][4 * k]) = make_ulonglong2(vA01, vA23);
        *reinterpret_cast<ulonglong2*>(&alphaB[t & 1][4 * k]) = make_ulonglong2(vB01, vB23);
        __syncthreads();
    }

    // ---- final argmin over 1024 states for both blocks (first-occurrence) ----
    {
        float vA0, vA1, vA2, vA3, vB0, vB1, vB2, vB3;
        upk2(vA0, vA1, vA01); upk2(vA2, vA3, vA23);
        upk2(vB0, vB1, vB01); upk2(vB2, vB3, vB23);
        float bm = vA0; int bi = 4 * k;
        if (vA1 < bm) { bm = vA1; bi = 4 * k + 1; }
        if (vA2 < bm) { bm = vA2; bi = 4 * k + 2; }
        if (vA3 < bm) { bm = vA3; bi = 4 * k + 3; }
        float cm = vB0; int ci = 4 * k;
        if (vB1 < cm) { cm = vB1; ci = 4 * k + 1; }
        if (vB2 < cm) { cm = vB2; ci = 4 * k + 2; }
        if (vB3 < cm) { cm = vB3; ci = 4 * k + 3; }
#pragma unroll
        for (int off = 16; off; off >>= 1) {
            float om = __shfl_down_sync(0xffffffffu, bm, off);
            int   oi = __shfl_down_sync(0xffffffffu, bi, off);
            if (om < bm || (om == bm && oi < bi)) { bm = om; bi = oi; }
            float pm = __shfl_down_sync(0xffffffffu, cm, off);
            int   pi = __shfl_down_sync(0xffffffffu, ci, off);
            if (pm < cm || (pm == cm && pi < ci)) { cm = pm; ci = pi; }
        }
        if ((k & 31) == 0) {
            redvA[k >> 5] = bm; rediA[k >> 5] = bi;
            redvB[k >> 5] = cm; rediB[k >> 5] = ci;
        }
    }
    __syncthreads();

    // ---- backtrack: thread 0 does A, thread 32 does B (parallel warps) ----
    if (k == 0) {
        float m = redvA[0]; int s = rediA[0];
#pragma unroll
        for (int w = 1; w < 8; ++w)
            if (redvA[w] < m || (redvA[w] == m && rediA[w] < s)) { m = redvA[w]; s = rediA[w]; }
        pathA[63] = s;
        for (int t = 63; t >= 1; --t) {
            int g = s >> 2;
            int j = bp[t][g] & 3;
            s = g + (j << 8);                // prev = (s>>2) + j*HI, HI = 256
            pathA[t - 1] = s;
        }
    }
    if (k == 32) {
        float m = redvB[0]; int s = rediB[0];
#pragma unroll
        for (int w = 1; w < 8; ++w)
            if (redvB[w] < m || (redvB[w] == m && rediB[w] < s)) { m = redvB[w]; s = rediB[w]; }
        pathB[63] = s;
        for (int t = 63; t >= 1; --t) {
            int g = s >> 2;
            int j = (bp[t][g] >> 2) & 3;
            s = g + (j << 8);
            pathB[t - 1] = s;
        }
    }
    __syncthreads();

    // ---- emit: rec (exact codebook gather) + states, both blocks ----
    if (k < 128) {
        int t = k & 63;
        bool isB = k >= 64;
        int s = isB ? pathB[t] : pathA[t];
        int bb = isB ? bB : bA;
        int br = isB ? brB : brA;
        int bc = isB ? bcB : bcA;
        float4 val = __ldg(cb4 + s);
        int row = br * 16 + (t >> 2);
        int col = bc * 16 + ((t & 3) << 2);
        reinterpret_cast<float4*>(out + row * ROWS + col)[0] = val;
        int sidx = ROWS * ROWS + bb * 64 + t;
        if (sidx < out_size) out[sidx] = (float)s;
    }
}

} // namespace

extern "C" void kernel_launch(void* const* d_in, const int* in_sizes, int n_in,
                              void* d_out, int out_size) {
    const float* array    = (const float*)d_in[0];
    const float* codebook = (const float*)d_in[1];
    (void)in_sizes; (void)n_in;
    float* out = (float*)d_out;
    viterbi_kernel<<<NCTA, NTH>>>(array, codebook, out, out_size);
}

// round 8
// speedup vs baseline: 1.0607x; 1.0607x over previous
#include <cuda_runtime.h>
#include <cstdint>

namespace {

constexpr int NTH  = 256;
constexpr int NCTA = 1366;   // ceil(4096 / 3) blocks per CTA
constexpr int ROWS = 1024;

// cost chain: cn + cb.x*x.x + ... where x is pre-scaled by -2 (|x|^2 term dropped:
// constant across states per step, cannot change any argmin)
__device__ __forceinline__ float costf(const float4 cb, float cn, const float4 x) {
    return fmaf(cb.w, x.w, fmaf(cb.z, x.z, fmaf(cb.y, x.y, fmaf(cb.x, x.x, cn))));
}
__device__ __forceinline__ float cnrm(const float4 c) {
    return fmaf(c.w, c.w, fmaf(c.z, c.z, fmaf(c.y, c.y, c.x * c.x)));
}

__global__ __launch_bounds__(NTH, 4)
void viterbi_kernel(const float* __restrict__ array,
                    const float* __restrict__ codebook,
                    float* __restrict__ out,
                    int out_size)
{
    __shared__ float alphaA[2][1024];
    __shared__ float alphaB[2][1024];
    __shared__ float alphaC[2][1024];
    __shared__ float4 xsA[64];
    __shared__ float4 xsB[64];
    __shared__ float4 xsC[64];
    __shared__ unsigned char bp[64][NTH];   // jA bits[1:0], jB bits[3:2], jC bits[5:4]
    __shared__ int   pathA[64], pathB[64], pathC[64];
    __shared__ float redvA[8], redvB[8], redvC[8];
    __shared__ int   rediA[8], rediB[8], rediC[8];

    const int k  = threadIdx.x;             // state group: owns states 4k..4k+3
    const int bA = 3 * blockIdx.x;
    const int bB = bA + 1;
    const int bC = bA + 2;
    const int bBc = bB < 4096 ? bB : 4095;  // clamp (last CTA duplicates block 4095)
    const int bCc = bC < 4096 ? bC : 4095;
    const int brA = bA >> 6,  bcA = bA & 63;
    const int brB = bBc >> 6, bcB = bBc & 63;
    const int brC = bCc >> 6, bcC = bCc & 63;

    // ---- load all three blocks' elements, pre-scaled by -2 ----
    {
        int r = k >> 4, cc = k & 15;
        float vA = array[(brA * 16 + r) * ROWS + (bcA * 16 + cc)];
        float vB = array[(brB * 16 + r) * ROWS + (bcB * 16 + cc)];
        float vC = array[(brC * 16 + r) * ROWS + (bcC * 16 + cc)];
        reinterpret_cast<float*>(xsA)[k] = -2.0f * vA;
        reinterpret_cast<float*>(xsB)[k] = -2.0f * vB;
        reinterpret_cast<float*>(xsC)[k] = -2.0f * vC;
    }

    // ---- codebook rows 4k..4k+3 in registers (shared by all three chains) ----
    const float4* cb4 = reinterpret_cast<const float4*>(codebook);
    float4 o0 = __ldg(cb4 + 4 * k + 0);
    float4 o1 = __ldg(cb4 + 4 * k + 1);
    float4 o2 = __ldg(cb4 + 4 * k + 2);
    float4 o3 = __ldg(cb4 + 4 * k + 3);
    float cn0 = cnrm(o0), cn1 = cnrm(o1), cn2 = cnrm(o2), cn3 = cnrm(o3);

    __syncthreads();

    // ---- alpha_0 = cost(x0) for all blocks ----
    float vA0, vA1, vA2, vA3, vB0, vB1, vB2, vB3, vC0, vC1, vC2, vC3;
    {
        float4 xA = xsA[0], xB = xsB[0], xC = xsC[0];
        vA0 = costf(o0, cn0, xA); vA1 = costf(o1, cn1, xA);
        vA2 = costf(o2, cn2, xA); vA3 = costf(o3, cn3, xA);
        vB0 = costf(o0, cn0, xB); vB1 = costf(o1, cn1, xB);
        vB2 = costf(o2, cn2, xB); vB3 = costf(o3, cn3, xB);
        vC0 = costf(o0, cn0, xC); vC1 = costf(o1, cn1, xC);
        vC2 = costf(o2, cn2, xC); vC3 = costf(o3, cn3, xC);
        *reinterpret_cast<float4*>(&alphaA[0][4 * k]) = make_float4(vA0, vA1, vA2, vA3);
        *reinterpret_cast<float4*>(&alphaB[0][4 * k]) = make_float4(vB0, vB1, vB2, vB3);
        *reinterpret_cast<float4*>(&alphaC[0][4 * k]) = make_float4(vC0, vC1, vC2, vC3);
    }
    __syncthreads();

    // ---- forward recursion: 63 steps, three independent chains interleaved ----
#pragma unroll 2
    for (int t = 1; t < 64; ++t) {
        const float* apA = alphaA[(t + 1) & 1];
        const float* apB = alphaB[(t + 1) & 1];
        const float* apC = alphaC[(t + 1) & 1];
        float aA0 = apA[k], aA1 = apA[k + 256], aA2 = apA[k + 512], aA3 = apA[k + 768];
        float aB0 = apB[k], aB1 = apB[k + 256], aB2 = apB[k + 512], aB3 = apB[k + 768];
        float aC0 = apC[k], aC1 = apC[k + 256], aC2 = apC[k + 512], aC3 = apC[k + 768];

        float mA = aA0; int jA = 0;          // strict < -> first-occurrence argmin
        if (aA1 < mA) { mA = aA1; jA = 1; }
        if (aA2 < mA) { mA = aA2; jA = 2; }
        if (aA3 < mA) { mA = aA3; jA = 3; }
        float mB = aB0; int jB = 0;
        if (aB1 < mB) { mB = aB1; jB = 1; }
        if (aB2 < mB) { mB = aB2; jB = 2; }
        if (aB3 < mB) { mB = aB3; jB = 3; }
        float mC = aC0; int jC = 0;
        if (aC1 < mC) { mC = aC1; jC = 1; }
        if (aC2 < mC) { mC = aC2; jC = 2; }
        if (aC3 < mC) { mC = aC3; jC = 3; }
        bp[t][k] = (unsigned char)(jA | (jB << 2) | (jC << 4));

        float4 xA = xsA[t], xB = xsB[t], xC = xsC[t];
        vA0 = mA + costf(o0, cn0, xA); vA1 = mA + costf(o1, cn1, xA);
        vA2 = mA + costf(o2, cn2, xA); vA3 = mA + costf(o3, cn3, xA);
        vB0 = mB + costf(o0, cn0, xB); vB1 = mB + costf(o1, cn1, xB);
        vB2 = mB + costf(o2, cn2, xB); vB3 = mB + costf(o3, cn3, xB);
        vC0 = mC + costf(o0, cn0, xC); vC1 = mC + costf(o1, cn1, xC);
        vC2 = mC + costf(o2, cn2, xC); vC3 = mC + costf(o3, cn3, xC);
        *reinterpret_cast<float4*>(&alphaA[t & 1][4 * k]) = make_float4(vA0, vA1, vA2, vA3);
        *reinterpret_cast<float4*>(&alphaB[t & 1][4 * k]) = make_float4(vB0, vB1, vB2, vB3);
        *reinterpret_cast<float4*>(&alphaC[t & 1][4 * k]) = make_float4(vC0, vC1, vC2, vC3);
        __syncthreads();
    }

    // ---- final argmin over 1024 states for all blocks (first-occurrence) ----
    {
        float bm = vA0; int bi = 4 * k;
        if (vA1 < bm) { bm = vA1; bi = 4 * k + 1; }
        if (vA2 < bm) { bm = vA2; bi = 4 * k + 2; }
        if (vA3 < bm) { bm = vA3; bi = 4 * k + 3; }
        float cm = vB0; int ci = 4 * k;
        if (vB1 < cm) { cm = vB1; ci = 4 * k + 1; }
        if (vB2 < cm) { cm = vB2; ci = 4 * k + 2; }
        if (vB3 < cm) { cm = vB3; ci = 4 * k + 3; }
        float dm = vC0; int di = 4 * k;
        if (vC1 < dm) { dm = vC1; di = 4 * k + 1; }
        if (vC2 < dm) { dm = vC2; di = 4 * k + 2; }
        if (vC3 < dm) { dm = vC3; di = 4 * k + 3; }
#pragma unroll
        for (int off = 16; off; off >>= 1) {
            float om = __shfl_down_sync(0xffffffffu, bm, off);
            int   oi = __shfl_down_sync(0xffffffffu, bi, off);
            if (om < bm || (om == bm && oi < bi)) { bm = om; bi = oi; }
            float pm = __shfl_down_sync(0xffffffffu, cm, off);
            int   pi = __shfl_down_sync(0xffffffffu, ci, off);
            if (pm < cm || (pm == cm && pi < ci)) { cm = pm; ci = pi; }
            float qm = __shfl_down_sync(0xffffffffu, dm, off);
            int   qi = __shfl_down_sync(0xffffffffu, di, off);
            if (qm < dm || (qm == dm && qi < di)) { dm = qm; di = qi; }
        }
        if ((k & 31) == 0) {
            redvA[k >> 5] = bm; rediA[k >> 5] = bi;
            redvB[k >> 5] = cm; rediB[k >> 5] = ci;
            redvC[k >> 5] = dm; rediC[k >> 5] = di;
        }
    }
    __syncthreads();

    // ---- backtrack: threads 0 / 32 / 64 handle A / B / C (parallel warps) ----
    if (k == 0) {
        float m = redvA[0]; int s = rediA[0];
#pragma unroll
        for (int w = 1; w < 8; ++w)
            if (redvA[w] < m || (redvA[w] == m && rediA[w] < s)) { m = redvA[w]; s = rediA[w]; }
        pathA[63] = s;
        for (int t = 63; t >= 1; --t) {
            int g = s >> 2;
            int j = bp[t][g] & 3;
            s = g + (j << 8);                // prev = (s>>2) + j*HI, HI = 256
            pathA[t - 1] = s;
        }
    }
    if (k == 32) {
        float m = redvB[0]; int s = rediB[0];
#pragma unroll
        for (int w = 1; w < 8; ++w)
            if (redvB[w] < m || (redvB[w] == m && rediB[w] < s)) { m = redvB[w]; s = rediB[w]; }
        pathB[63] = s;
        for (int t = 63; t >= 1; --t) {
            int g = s >> 2;
            int j = (bp[t][g] >> 2) & 3;
            s = g + (j << 8);
            pathB[t - 1] = s;
        }
    }
    if (k == 64) {
        float m = redvC[0]; int s = rediC[0];
#pragma unroll
        for (int w = 1; w < 8; ++w)
            if (redvC[w] < m || (redvC[w] == m && rediC[w] < s)) { m = redvC[w]; s = rediC[w]; }
        pathC[63] = s;
        for (int t = 63; t >= 1; --t) {
            int g = s >> 2;
            int j = (bp[t][g] >> 4) & 3;
            s = g + (j << 8);
            pathC[t - 1] = s;
        }
    }
    __syncthreads();

    // ---- emit: rec (exact codebook gather) + states, all valid blocks ----
    if (k < 192) {
        int t   = k & 63;
        int sel = k >> 6;                    // 0=A, 1=B, 2=C
        int bb  = bA + sel;
        if (bb < 4096) {
            int s = (sel == 0) ? pathA[t] : (sel == 1) ? pathB[t] : pathC[t];
            int br = bb >> 6, bc = bb & 63;
            float4 val = __ldg(cb4 + s);
            int row = br * 16 + (t >> 2);
            int col = bc * 16 + ((t & 3) << 2);
            reinterpret_cast<float4*>(out + row * ROWS + col)[0] = val;
            int sidx = ROWS * ROWS + bb * 64 + t;
            if (sidx < out_size) out[sidx] = (float)s;
        }
    }
}

} // namespace

extern "C" void kernel_launch(void* const* d_in, const int* in_sizes, int n_in,
                              void* d_out, int out_size) {
    const float* array    = (const float*)d_in[0];
    const float* codebook = (const float*)d_in[1];
    (void)in_sizes; (void)n_in;
    float* out = (float*)d_out;
    viterbi_kernel<<<NCTA, NTH>>>(array, codebook, out, out_size);
}